// round 8
// baseline (speedup 1.0000x reference)
#include <cuda_runtime.h>
#include <cuda_bf16.h>
#include <mma.h>
#include <math.h>

using namespace nvcuda;

#define HID 128
#define NHEAD 4
#define CDIM 128
#define HC 512
#define NLAYER 3
#define NMAX 10240
#define BMAX 64
#define EMAX (160000 + NMAX + 768)

// ---------------- device scratch ----------------
static __device__ __align__(16) float g_h   [(size_t)NMAX * HID];
static __device__ __align__(16) float g_hw  [(size_t)NMAX * HC];
static __device__ __align__(16) __nv_bfloat16 g_Ahi[(size_t)NMAX * HID];
static __device__ __align__(16) __nv_bfloat16 g_Alo[(size_t)NMAX * HID];
static __device__ __align__(16) __nv_bfloat16 g_Whi[(size_t)NLAYER * HID * HC];
static __device__ __align__(16) __nv_bfloat16 g_Wlo[(size_t)NLAYER * HID * HC];
static __device__ __align__(16) float g_asrc[NMAX * NHEAD];
static __device__ __align__(16) float g_adst[NMAX * NHEAD];
static __device__ __align__(16) float g_gmax[NHEAD];
static __device__ __align__(16) float g_out [(size_t)NMAX * HID];
static __device__ __align__(16) float g_pool[BMAX * HID];
static __device__ float g_cnt [BMAX];
static __device__ int   g_is64;
// CSR by dst: adj holds SRC node ids
static __device__ int g_deg[NMAX];
static __device__ int g_ptr[NMAX];
static __device__ int g_cur[NMAX];
static __device__ int g_adj[EMAX];

// ---------------- helpers ----------------
__device__ __forceinline__ float lrelu(float x) { return x > 0.f ? x : 0.2f * x; }

__device__ __forceinline__ void atomicMaxF(float* a, float v) {
    if (v >= 0.f) atomicMax((int*)a, __float_as_int(v));
    else          atomicMin((unsigned int*)a, __float_as_uint(v));
}

__device__ __forceinline__ void redAdd1(float* p, float v) {
    asm volatile("red.global.add.f32 [%0], %1;" :: "l"(p), "f"(v) : "memory");
}

__device__ __forceinline__ int idx_at(const void* p, int i, int is64) {
    return is64 ? (int)((const long long*)p)[i] : ((const int*)p)[i];
}

// ---------------- CSR build (by dst) ----------------
__global__ void k_csr0(const void* ei, int M) {
    int i = blockIdx.x * blockDim.x + threadIdx.x;
    if (i < M) g_deg[i] = 0;
    if (i == 0) {
        const long long* p = (const long long*)ei;
        int ok = 1;
        for (int k = 0; k < 16; k++) {
            long long v = p[k];
            if (v < 0 || v >= (long long)M) { ok = 0; break; }
        }
        g_is64 = ok;
    }
}

__global__ void k_hist(const void* __restrict__ ei, int E, int M) {
    int i = blockIdx.x * blockDim.x + threadIdx.x;
    if (i >= E + M) return;
    int d = (i < E) ? idx_at(ei, E + i, g_is64) : (i - E);
    atomicAdd(&g_deg[d], 1);
}

// single-block shfl-scan: 1024 threads, register-resident chunks
__global__ void k_scan(int M) {
    __shared__ int ws[32];
    int t = threadIdx.x;
    int chunk = (M + 1023) >> 10;
    int start = t * chunk;
    int loc[16];
    int sum = 0;
#pragma unroll 16
    for (int i = 0; i < chunk; i++) {
        int idx = start + i;
        int v = (idx < M) ? g_deg[idx] : 0;
        loc[i] = sum;
        sum += v;
    }
    int lane = t & 31, wid = t >> 5;
    int x = sum;
#pragma unroll
    for (int o = 1; o < 32; o <<= 1) {
        int y = __shfl_up_sync(~0u, x, o);
        if (lane >= o) x += y;
    }
    if (lane == 31) ws[wid] = x;
    __syncthreads();
    if (wid == 0) {
        int y = ws[lane];
#pragma unroll
        for (int o = 1; o < 32; o <<= 1) {
            int z = __shfl_up_sync(~0u, y, o);
            if (lane >= o) y += z;
        }
        ws[lane] = y;
    }
    __syncthreads();
    int base = (x - sum) + (wid ? ws[wid - 1] : 0);
#pragma unroll 16
    for (int i = 0; i < chunk; i++) {
        int idx = start + i;
        if (idx < M) {
            int p = base + loc[i];
            g_ptr[idx] = p;
            g_cur[idx] = p;
        }
    }
}

__global__ void k_fill(const void* __restrict__ ei, int E, int M) {
    int i = blockIdx.x * blockDim.x + threadIdx.x;
    if (i >= E + M) return;
    int is64 = g_is64;
    int s, d;
    if (i < E) { s = idx_at(ei, i, is64); d = idx_at(ei, E + i, is64); } else { s = d = i - E; }
    int pos = atomicAdd(&g_cur[d], 1);
    g_adj[pos] = s;
}

// ---------------- main kernels ----------------

// h0 = relu(x @ node_W + node_b); bf16 split; zero gmax/pool
__global__ void k_init(const float* __restrict__ x, const float* __restrict__ W,
                       const float* __restrict__ b, int M) {
    int i = blockIdx.x * blockDim.x + threadIdx.x;
    if (i >= M * HID) return;
    int n = i >> 7, j = i & 127;
    float acc = b[j];
#pragma unroll
    for (int k = 0; k < 5; k++) acc += x[n * 5 + k] * W[k * HID + j];
    float h = fmaxf(acc, 0.f);
    g_h[i] = h;
    __nv_bfloat16 hi = __float2bfloat16(h);
    g_Ahi[i] = hi;
    g_Alo[i] = __float2bfloat16(h - __bfloat162float(hi));
    if (i < NHEAD) g_gmax[i] = -1e30f;
    if (i < BMAX * HID) g_pool[i] = 0.f;
    if (i < BMAX) g_cnt[i] = 0.f;
}

__global__ void k_convW(const float* __restrict__ Ws) {
    int i = blockIdx.x * blockDim.x + threadIdx.x;
    if (i >= NLAYER * HID * HC) return;
    float w = Ws[i];
    __nv_bfloat16 hi = __float2bfloat16(w);
    g_Whi[i] = hi;
    g_Wlo[i] = __float2bfloat16(w - __bfloat162float(hi));
}

// GEMM 64(M) x 128(N=head), smem-staged bf16x3 wmma + fused attention epilogue
__global__ void k_gemm(const __nv_bfloat16* __restrict__ Whi,
                       const __nv_bfloat16* __restrict__ Wlo,
                       const float* __restrict__ att_src,
                       const float* __restrict__ att_dst, int M) {
    __shared__ __align__(16) unsigned char sm_raw[64 * 132 * 4];
    __nv_bfloat16* Ahi = (__nv_bfloat16*)sm_raw;                  // [64][48]
    __nv_bfloat16* Alo = Ahi + 64 * 48;
    __nv_bfloat16* Bhi = (__nv_bfloat16*)(sm_raw + 12288);        // [32][136]
    __nv_bfloat16* Blo = Bhi + 32 * 136;
    float* Cs = (float*)sm_raw;                                   // [64][132]

    int head = blockIdx.x;
    int bm = blockIdx.y * 64;
    int tid = threadIdx.x;
    int w = tid >> 5, lane = tid & 31;
    int wm = w & 1, wn = w >> 1;

    wmma::fragment<wmma::accumulator, 16, 16, 16, float> acc[2][2];
#pragma unroll
    for (int i = 0; i < 2; i++)
#pragma unroll
        for (int j = 0; j < 2; j++) wmma::fill_fragment(acc[i][j], 0.f);

    for (int k0 = 0; k0 < 128; k0 += 32) {
        {
            int row = tid >> 2, c8 = (tid & 3) * 8;
            int grow = bm + row;
            uint4 vh = make_uint4(0, 0, 0, 0), vl = make_uint4(0, 0, 0, 0);
            if (grow < M) {
                vh = *(const uint4*)(g_Ahi + (size_t)grow * HID + k0 + c8);
                vl = *(const uint4*)(g_Alo + (size_t)grow * HID + k0 + c8);
            }
            *(uint4*)(Ahi + row * 48 + c8) = vh;
            *(uint4*)(Alo + row * 48 + c8) = vl;
        }
#pragma unroll
        for (int i = 0; i < 2; i++) {
            int idx = tid + i * 256;
            int r = idx >> 4, c8 = (idx & 15) * 8;
            *(uint4*)(Bhi + r * 136 + c8) =
                *(const uint4*)(Whi + (size_t)(k0 + r) * HC + head * 128 + c8);
            *(uint4*)(Blo + r * 136 + c8) =
                *(const uint4*)(Wlo + (size_t)(k0 + r) * HC + head * 128 + c8);
        }
        __syncthreads();
#pragma unroll
        for (int kk = 0; kk < 32; kk += 16) {
            wmma::fragment<wmma::matrix_a, 16, 16, 16, __nv_bfloat16, wmma::row_major> ahi[2], alo[2];
            wmma::fragment<wmma::matrix_b, 16, 16, 16, __nv_bfloat16, wmma::row_major> bhi[2], blo[2];
#pragma unroll
            for (int i = 0; i < 2; i++) {
                wmma::load_matrix_sync(ahi[i], Ahi + (wm * 32 + i * 16) * 48 + kk, 48);
                wmma::load_matrix_sync(alo[i], Alo + (wm * 32 + i * 16) * 48 + kk, 48);
                wmma::load_matrix_sync(bhi[i], Bhi + kk * 136 + wn * 32 + i * 16, 136);
                wmma::load_matrix_sync(blo[i], Blo + kk * 136 + wn * 32 + i * 16, 136);
            }
#pragma unroll
            for (int i = 0; i < 2; i++)
#pragma unroll
                for (int j = 0; j < 2; j++) {
                    wmma::mma_sync(acc[i][j], ahi[i], bhi[j], acc[i][j]);
                    wmma::mma_sync(acc[i][j], ahi[i], blo[j], acc[i][j]);
                    wmma::mma_sync(acc[i][j], alo[i], bhi[j], acc[i][j]);
                }
        }
        __syncthreads();
    }

#pragma unroll
    for (int i = 0; i < 2; i++)
#pragma unroll
        for (int j = 0; j < 2; j++)
            wmma::store_matrix_sync(Cs + (wm * 32 + i * 16) * 132 + wn * 32 + j * 16,
                                    acc[i][j], 132, wmma::mem_row_major);
    __syncthreads();

    float4 as4 = *(const float4*)(att_src + head * CDIM + lane * 4);
    float4 ad4 = *(const float4*)(att_dst + head * CDIM + lane * 4);
#pragma unroll
    for (int r = 0; r < 8; r++) {
        int row = w * 8 + r;
        int grow = bm + row;
        if (grow >= M) break;
        float4 c4 = *(float4*)(Cs + row * 132 + lane * 4);
        *(float4*)(g_hw + (size_t)grow * HC + head * CDIM + lane * 4) = c4;
        float ss = c4.x * as4.x + c4.y * as4.y + c4.z * as4.z + c4.w * as4.w;
        float sd = c4.x * ad4.x + c4.y * ad4.y + c4.z * ad4.z + c4.w * ad4.w;
#pragma unroll
        for (int o = 16; o; o >>= 1) {
            ss += __shfl_xor_sync(~0u, ss, o);
            sd += __shfl_xor_sync(~0u, sd, o);
        }
        if (lane == 0) {
            g_asrc[grow * 4 + head] = ss;
            g_adst[grow * 4 + head] = sd;
            atomicMaxF(&g_gmax[head], ss);
        }
    }
}

// Fused softmax + aggregate, CSR by dst, one warp per dst, zero atomics.
// out[d] = sum_h (sum_s ev_sh * hw[s,h,:]) * 0.25/(den_h + 1e-16)
__global__ void k_aggr(int M) {
    int gid = blockIdx.x * blockDim.x + threadIdx.x;
    int d = gid >> 5, lane = gid & 31;
    if (d >= M) return;
    float4 gm = *(const float4*)g_gmax;
    float4 ad = *(const float4*)(g_adst + d * 4);
    float4 md;
    md.x = lrelu(gm.x + ad.x); md.y = lrelu(gm.y + ad.y);
    md.z = lrelu(gm.z + ad.z); md.w = lrelu(gm.w + ad.w);

    float4 acc0 = {0.f, 0.f, 0.f, 0.f}, acc1 = acc0, acc2 = acc0, acc3 = acc0;
    float4 den = acc0;

    int base = g_ptr[d], cnt = g_deg[d];
    for (int j0 = 0; j0 < cnt; j0 += 32) {
        int j = j0 + lane;
        int s = 0;
        float4 ev = {0.f, 0.f, 0.f, 0.f};
        if (j < cnt) {
            s = g_adj[base + j];
            float4 as = *(const float4*)(g_asrc + s * 4);
            ev.x = __expf(lrelu(as.x + ad.x) - md.x);
            ev.y = __expf(lrelu(as.y + ad.y) - md.y);
            ev.z = __expf(lrelu(as.z + ad.z) - md.z);
            ev.w = __expf(lrelu(as.w + ad.w) - md.w);
            den.x += ev.x; den.y += ev.y; den.z += ev.z; den.w += ev.w;
        }
        int m = min(cnt - j0, 32);
        for (int jj = 0; jj < m; jj++) {
            int ss  = __shfl_sync(~0u, s, jj);
            float b0 = __shfl_sync(~0u, ev.x, jj);
            float b1 = __shfl_sync(~0u, ev.y, jj);
            float b2 = __shfl_sync(~0u, ev.z, jj);
            float b3 = __shfl_sync(~0u, ev.w, jj);
            const float4* hs = (const float4*)(g_hw + (size_t)ss * HC);
            float4 v0 = hs[lane];
            float4 v1 = hs[32 + lane];
            float4 v2 = hs[64 + lane];
            float4 v3 = hs[96 + lane];
            acc0.x += b0 * v0.x; acc0.y += b0 * v0.y; acc0.z += b0 * v0.z; acc0.w += b0 * v0.w;
            acc1.x += b1 * v1.x; acc1.y += b1 * v1.y; acc1.z += b1 * v1.z; acc1.w += b1 * v1.w;
            acc2.x += b2 * v2.x; acc2.y += b2 * v2.y; acc2.z += b2 * v2.z; acc2.w += b2 * v2.w;
            acc3.x += b3 * v3.x; acc3.y += b3 * v3.y; acc3.z += b3 * v3.z; acc3.w += b3 * v3.w;
        }
    }
    // reduce denominators across lanes
#pragma unroll
    for (int o = 16; o; o >>= 1) {
        den.x += __shfl_xor_sync(~0u, den.x, o);
        den.y += __shfl_xor_sync(~0u, den.y, o);
        den.z += __shfl_xor_sync(~0u, den.z, o);
        den.w += __shfl_xor_sync(~0u, den.w, o);
    }
    float r0 = 0.25f / (den.x + 1e-16f);
    float r1 = 0.25f / (den.y + 1e-16f);
    float r2 = 0.25f / (den.z + 1e-16f);
    float r3 = 0.25f / (den.w + 1e-16f);
    float4 o4;
    o4.x = acc0.x * r0 + acc1.x * r1 + acc2.x * r2 + acc3.x * r3;
    o4.y = acc0.y * r0 + acc1.y * r1 + acc2.y * r2 + acc3.y * r3;
    o4.z = acc0.z * r0 + acc1.z * r1 + acc2.z * r2 + acc3.z * r3;
    o4.w = acc0.w * r0 + acc1.w * r1 + acc2.w * r2 + acc3.w * r3;
    *(float4*)(g_out + (size_t)d * HID + lane * 4) = o4;
}

// bias + LN + relu + residual + next-layer prep; final layer also pools + writes out
__global__ void k_post(const float* __restrict__ bias, const float* __restrict__ lng,
                       const float* __restrict__ lnb, int M, float* __restrict__ dout,
                       const void* __restrict__ batch) {
    int n = blockIdx.x;
    if (n >= M) return;
    int t = threadIdx.x;
    size_t i = (size_t)n * HID + t;
    float v = g_out[i] + bias[t];
    __shared__ float sh[4];
    float s = v;
#pragma unroll
    for (int o = 16; o; o >>= 1) s += __shfl_xor_sync(~0u, s, o);
    if ((t & 31) == 0) sh[t >> 5] = s;
    __syncthreads();
    float mu = (sh[0] + sh[1] + sh[2] + sh[3]) * (1.f / 128.f);
    __syncthreads();
    float dv = v - mu;
    float q = dv * dv;
#pragma unroll
    for (int o = 16; o; o >>= 1) q += __shfl_xor_sync(~0u, q, o);
    if ((t & 31) == 0) sh[t >> 5] = q;
    __syncthreads();
    float var = (sh[0] + sh[1] + sh[2] + sh[3]) * (1.f / 128.f);
    float ln = dv * rsqrtf(var + 1e-5f) * lng[t] + lnb[t];
    float h = g_h[i] + fmaxf(ln, 0.f);
    g_h[i] = h;
    if (!dout) {
        __nv_bfloat16 hi = __float2bfloat16(h);
        g_Ahi[i] = hi;
        g_Alo[i] = __float2bfloat16(h - __bfloat162float(hi));
        if (n == 0 && t < NHEAD) g_gmax[t] = -1e30f;
    } else {
        dout[i] = h;
        int b = idx_at(batch, n, g_is64);
        redAdd1(g_pool + b * HID + t, h);
        if (t == 0) redAdd1(g_cnt + b, 1.f);
    }
}

__global__ void k_write_pool(float* __restrict__ dout, int M, int tail) {
    int i = blockIdx.x * blockDim.x + threadIdx.x;
    if (i >= tail) return;
    dout[(size_t)M * HID + i] = g_pool[i] / fmaxf(g_cnt[i >> 7], 1.f);
}

// ---------------- launch ----------------
extern "C" void kernel_launch(void* const* d_in, const int* in_sizes, int n_in,
                              void* d_out, int out_size) {
    const float* x        = (const float*)d_in[0];
    const void*  ei       = d_in[1];
    const void*  batch    = d_in[2];
    const float* node_W   = (const float*)d_in[3];
    const float* node_b   = (const float*)d_in[4];
    const float* Ws       = (const float*)d_in[5];
    const float* att_srcs = (const float*)d_in[6];
    const float* att_dsts = (const float*)d_in[7];
    const float* biases   = (const float*)d_in[8];
    const float* ln_gs    = (const float*)d_in[9];
    const float* ln_bs    = (const float*)d_in[10];

    int M = in_sizes[2];
    int E = in_sizes[1] / 2;
    int EM = E + M;
    float* dout = (float*)d_out;

    k_csr0<<<(M + 255) / 256, 256>>>(ei, M);
    k_hist<<<(EM + 255) / 256, 256>>>(ei, E, M);
    k_scan<<<1, 1024>>>(M);
    k_fill<<<(EM + 255) / 256, 256>>>(ei, E, M);

    k_init<<<(M * HID + 255) / 256, 256>>>(x, node_W, node_b, M);
    k_convW<<<(NLAYER * HID * HC + 255) / 256, 256>>>(Ws);

    __nv_bfloat16* whi_base;
    __nv_bfloat16* wlo_base;
    cudaGetSymbolAddress((void**)&whi_base, g_Whi);
    cudaGetSymbolAddress((void**)&wlo_base, g_Wlo);

    for (int l = 0; l < NLAYER; l++) {
        k_gemm<<<dim3(NHEAD, (M + 63) / 64), 256>>>(whi_base + (size_t)l * HID * HC,
                                                    wlo_base + (size_t)l * HID * HC,
                                                    att_srcs + l * HC, att_dsts + l * HC, M);
        k_aggr<<<((size_t)M * 32 + 255) / 256, 256>>>(M);
        k_post<<<M, 128>>>(biases + l * HID, ln_gs + l * HID, ln_bs + l * HID, M,
                           (l == NLAYER - 1) ? dout : nullptr, batch);
    }

    k_write_pool<<<(out_size - M * HID + 255) / 256, 256>>>(dout, M, out_size - M * HID);
}